// round 10
// baseline (speedup 1.0000x reference)
#include <cuda_runtime.h>
#include <cuda_bf16.h>
#include <math.h>

// Shapes: x, mix: [8,192,64,64] fp32 ; W: [191,192] ; b: [191]
// Outputs: ybar then mix_out, each 6291456 floats, contiguous in d_out.
#define CCH   192
#define TT    16              // channel tile
#define NTIL  12              // 192/16
#define BLOCK 128             // threads per block
#define PIX_PER_BLOCK 256     // 2 adjacent pixels per thread
#define NPIX  32768           // 8*64*64
#define NCHW  6291456         // 8*192*64*64
#define ACC_F4_STRIDE 97      // float4 stride per thread: 97*4=388 floats -> conflict-free
#define WREG  6               // prefetch registers for W slab (max 764 float4 / 128 thr)

typedef unsigned long long u64;

// ---- packed f32x2 helpers (sm_103a FFMA2 path, PTX-only) ----
__device__ __forceinline__ u64 pack2(float a, float b) {
    u64 r; asm("mov.b64 %0, {%1,%2};" : "=l"(r) : "f"(a), "f"(b)); return r;
}
__device__ __forceinline__ u64 fma2(u64 a, u64 b, u64 c) {
    u64 d; asm("fma.rn.f32x2 %0, %1, %2, %3;" : "=l"(d) : "l"(a), "l"(b), "l"(c)); return d;
}
__device__ __forceinline__ float red2(u64 v) {
    float a, b; asm("mov.b64 {%0,%1}, %2;" : "=f"(a), "=f"(b) : "l"(v)); return a + b;
}

__global__ void __launch_bounds__(BLOCK, 1)
chan_deps_kernel(const float* __restrict__ x,
                 const float* __restrict__ mix,
                 const float* __restrict__ W,
                 const float* __restrict__ b,
                 float* __restrict__ ybar_out,
                 float* __restrict__ mix_out)
{
    extern __shared__ float smem[];
    float4* acc4 = reinterpret_cast<float4*>(smem);            // [BLOCK][ACC_F4_STRIDE]
    float*  Wc   = smem + 4 * BLOCK * ACC_F4_STRIDE;           // slab: up to 191*16 floats
    float*  bs   = Wc + 191 * TT;                              // bias, 191 floats

    const int tid = threadIdx.x;
    const int p0  = blockIdx.x * PIX_PER_BLOCK + 2 * tid;      // even pixel; p1 = p0+1
    const int n   = p0 >> 12;
    const int hw  = p0 & 4095;
    const int base = ((n * CCH) << 12) + hw;                   // fp32 index of (n, c=0, hw)

    float4* accp4 = acc4 + tid * ACC_F4_STRIDE;

    // zero accumulators: acc4[k] = {c=2k px0, c=2k px1, c=2k+1 px0, c=2k+1 px1}
    {
        const float4 z = make_float4(0.f, 0.f, 0.f, 0.f);
        #pragma unroll 8
        for (int k = 0; k < CCH / 2; k++) accp4[k] = z;
    }
    // stage bias
    for (int i = tid; i < CCH - 1; i += BLOCK) bs[i] = __ldg(&b[i]);

    // prologue: prefetch W slab for tile 0 into registers
    float4 wreg[WREG];
    {
        const int cnt = 191 * 4;   // nrows(t=0)=191, 4 float4 per row
        #pragma unroll
        for (int k = 0; k < WREG; k++) {
            const int idx = tid + k * BLOCK;
            if (idx < cnt) {
                const int r = idx >> 2, q = idx & 3;
                wreg[k] = __ldg(reinterpret_cast<const float4*>(W + r * CCH) + q);
            }
        }
    }

    for (int t = 0; t < NTIL; t++) {
        const int cbase = t * TT;
        const int cend  = cbase + TT;
        const int cnt   = (191 - cbase) * 4;   // float4s in this tile's slab

        __syncthreads();                        // prior tile's Wc readers done
        #pragma unroll
        for (int k = 0; k < WREG; k++) {
            const int idx = tid + k * BLOCK;
            if (idx < cnt) reinterpret_cast<float4*>(Wc)[idx] = wreg[k];
        }
        __syncthreads();

        // prefetch next tile's slab into regs (hidden behind this tile's compute)
        if (t + 1 < NTIL) {
            const int cb2  = cbase + TT;
            const int cnt2 = (191 - cb2) * 4;
            #pragma unroll
            for (int k = 0; k < WREG; k++) {
                const int idx = tid + k * BLOCK;
                if (idx < cnt2) {
                    const int r = idx >> 2, q = idx & 3;
                    wreg[k] = __ldg(reinterpret_cast<const float4*>(W + (cb2 + r) * CCH + cb2) + q);
                }
            }
        }

        // ---- load this tile's x / mix for the adjacent pixel pair (LDG.64)
        float2 xv2[TT], mv2[TT];
        #pragma unroll
        for (int i = 0; i < TT; i++) {
            const int gi = base + ((cbase + i) << 12);
            xv2[i] = __ldg(reinterpret_cast<const float2*>(x + gi));
            mv2[i] = __ldg(reinterpret_cast<const float2*>(mix + gi));
        }

        // ---- sequential in-tile recurrence (scalar; inherently serial)
        float part0[TT], part1[TT];
        #pragma unroll
        for (int i = 0; i < TT; i++) { part0[i] = 0.f; part1[i] = 0.f; }

        float yr0[TT], yr1[TT];
        float4 a4;
        #pragma unroll
        for (int i = 0; i < TT; i++) {
            const int c = cbase + i;
            if ((i & 1) == 0) a4 = accp4[c >> 1];          // LDS.128, 2 channels x 2 px
            float m0, m1;
            if (i == 0 && cbase == 0) {                     // channel 0: no conv/bias
                m0 = mv2[0].x;
                m1 = mv2[0].y;
            } else {
                const float av0 = (i & 1) ? a4.z : a4.x;
                const float av1 = (i & 1) ? a4.w : a4.y;
                const float bb  = bs[c - 1];
                m0 = av0 + bb + mv2[i].x + part0[i];
                m1 = av1 + bb + mv2[i].y + part1[i];
            }
            const float y0 = rintf(xv2[i].x - m0) + m0;     // half-to-even = jnp.round
            const float y1 = rintf(xv2[i].y - m1) + m1;
            yr0[i] = y0; yr1[i] = y1;
            const int gi = base + (c << 12);
            *reinterpret_cast<float2*>(ybar_out + gi) = make_float2(y0, y1);
            *reinterpret_cast<float2*>(mix_out  + gi) = make_float2(m0, m1);
            #pragma unroll
            for (int i2 = i + 1; i2 < TT; i2++) {
                const float w = Wc[(i2 - 1) * TT + i];      // uniform broadcast
                part0[i2] = fmaf(w, y0, part0[i2]);
                part1[i2] = fmaf(w, y1, part1[i2]);
            }
        }

        // ---- pack y pairs along j for f32x2 dot products
        u64 yp0[8], yp1[8];
        #pragma unroll
        for (int k = 0; k < 8; k++) {
            yp0[k] = pack2(yr0[2 * k], yr0[2 * k + 1]);
            yp1[k] = pack2(yr1[2 * k], yr1[2 * k + 1]);
        }

        // ---- cross-tile rank-16 update with FFMA2: 4 future channels per group
        for (int c2 = cend; c2 < CCH; c2 += 4) {
            const ulonglong2* wr0 = reinterpret_cast<const ulonglong2*>(Wc + (c2 - 1 - cbase) * TT);
            const ulonglong2* wr1 = reinterpret_cast<const ulonglong2*>(Wc + (c2     - cbase) * TT);
            const ulonglong2* wr2 = reinterpret_cast<const ulonglong2*>(Wc + (c2 + 1 - cbase) * TT);
            const ulonglong2* wr3 = reinterpret_cast<const ulonglong2*>(Wc + (c2 + 2 - cbase) * TT);
            u64 s00 = 0, s01 = 0, s10 = 0, s11 = 0, s20 = 0, s21 = 0, s30 = 0, s31 = 0;
            #pragma unroll
            for (int q = 0; q < 4; q++) {                   // 4 x LDS.128 per row
                const ulonglong2 wA = wr0[q];
                s00 = fma2(wA.x, yp0[2 * q], s00); s00 = fma2(wA.y, yp0[2 * q + 1], s00);
                s01 = fma2(wA.x, yp1[2 * q], s01); s01 = fma2(wA.y, yp1[2 * q + 1], s01);
                const ulonglong2 wB = wr1[q];
                s10 = fma2(wB.x, yp0[2 * q], s10); s10 = fma2(wB.y, yp0[2 * q + 1], s10);
                s11 = fma2(wB.x, yp1[2 * q], s11); s11 = fma2(wB.y, yp1[2 * q + 1], s11);
                const ulonglong2 wC = wr2[q];
                s20 = fma2(wC.x, yp0[2 * q], s20); s20 = fma2(wC.y, yp0[2 * q + 1], s20);
                s21 = fma2(wC.x, yp1[2 * q], s21); s21 = fma2(wC.y, yp1[2 * q + 1], s21);
                const ulonglong2 wD = wr3[q];
                s30 = fma2(wD.x, yp0[2 * q], s30); s30 = fma2(wD.y, yp0[2 * q + 1], s30);
                s31 = fma2(wD.x, yp1[2 * q], s31); s31 = fma2(wD.y, yp1[2 * q + 1], s31);
            }
            const int k = c2 >> 1;
            float4 a0 = accp4[k];
            float4 a1 = accp4[k + 1];
            a0.x += red2(s00); a0.y += red2(s01); a0.z += red2(s10); a0.w += red2(s11);
            a1.x += red2(s20); a1.y += red2(s21); a1.z += red2(s30); a1.w += red2(s31);
            accp4[k]     = a0;
            accp4[k + 1] = a1;
        }
    }
}

extern "C" void kernel_launch(void* const* d_in, const int* in_sizes, int n_in,
                              void* d_out, int out_size)
{
    const float* x   = (const float*)d_in[0];
    const float* mix = (const float*)d_in[1];
    const float* W   = (const float*)d_in[2];
    const float* b   = (const float*)d_in[3];

    float* ybar_out = (float*)d_out;
    float* mix_out  = (float*)d_out + NCHW;

    const size_t smem_bytes =
        (size_t)(4 * BLOCK * ACC_F4_STRIDE + 191 * TT + 191) * sizeof(float);  // ~212 KB
    cudaFuncSetAttribute(chan_deps_kernel,
                         cudaFuncAttributeMaxDynamicSharedMemorySize,
                         (int)smem_bytes);

    const int grid = NPIX / PIX_PER_BLOCK;       // 128, single balanced wave
    chan_deps_kernel<<<grid, BLOCK, smem_bytes>>>(x, mix, W, b, ybar_out, mix_out);
}

// round 12
// speedup vs baseline: 1.0845x; 1.0845x over previous
#include <cuda_runtime.h>
#include <cuda_bf16.h>
#include <math.h>

// Shapes: x, mix: [8,192,64,64] fp32 ; W: [191,192] ; b: [191]
// Outputs: ybar then mix_out, each 6291456 floats, contiguous in d_out.
#define CCH   192
#define TT    16
#define NTIL  12
#define BLOCK 128
#define PIX_PER_BLOCK 256      // 2 adjacent pixels per thread
#define NPIX  32768
#define NCHW  6291456
#define ACC_F4_STRIDE 97       // float4 stride/thread: conflict-free, 16B aligned

typedef unsigned long long u64;

__device__ __forceinline__ u64 pack2(float a, float b) {
    u64 r; asm("mov.b64 %0, {%1,%2};" : "=l"(r) : "f"(a), "f"(b)); return r;
}
__device__ __forceinline__ u64 fma2(u64 a, u64 b, u64 c) {
    u64 d; asm("fma.rn.f32x2 %0, %1, %2, %3;" : "=l"(d) : "l"(a), "l"(b), "l"(c)); return d;
}
__device__ __forceinline__ u64 add2(u64 a, u64 b) {
    u64 d; asm("add.rn.f32x2 %0, %1, %2;" : "=l"(d) : "l"(a), "l"(b)); return d;
}

// smem budget: acc 128*97*16B = 198656, Wx 88*16*8B = 11264, Wd 240*8B = 1920,
// bs 191*4B = 764  -> 212604 B (~207.6 KB) < 227 KB
__global__ void __launch_bounds__(BLOCK, 1)
chan_deps_kernel(const float* __restrict__ x,
                 const float* __restrict__ mix,
                 const float* __restrict__ W,
                 const float* __restrict__ b,
                 float* __restrict__ ybar_out,
                 float* __restrict__ mix_out)
{
    extern __shared__ float smem[];
    float4* acc4 = reinterpret_cast<float4*>(smem);                 // [128][97]
    u64*    Wx   = reinterpret_cast<u64*>(smem + 4 * BLOCK * ACC_F4_STRIDE); // 88*16
    u64*    Wd   = Wx + 88 * TT;                                    // 240 dup pairs (tri)
    float*  bs   = reinterpret_cast<float*>(Wd + 240);              // 191

    const int tid  = threadIdx.x;
    const int p0   = blockIdx.x * PIX_PER_BLOCK + 2 * tid;          // even pixel
    const int base = (((p0 >> 12) * CCH) << 12) + (p0 & 4095);

    float4* accp4 = acc4 + tid * ACC_F4_STRIDE;

    // zero accumulators: acc4[k] = (acc[2k]p0, acc[2k+1]p0, acc[2k]p1, acc[2k+1]p1)
    {
        const float4 z = make_float4(0.f, 0.f, 0.f, 0.f);
        #pragma unroll 8
        for (int k = 0; k < CCH / 2; k++) accp4[k] = z;
    }
    for (int i = tid; i < CCH - 1; i += BLOCK) bs[i] = __ldg(&b[i]);

    // ---- direct-stage tile 0 slabs ----
    {
        // cross slab: Wx[pr*16 + j] = (W[c2-1][j], W[c2][j]), c2 = 16 + 2*pr
        const int tasks = 88 * 4;                    // (pr, j-quad)
        for (int k = tid; k < tasks; k += BLOCK) {
            const int pr = k >> 2, q = k & 3, c2 = TT + 2 * pr, col = 4 * q;
            const float4 wa = __ldg(reinterpret_cast<const float4*>(W + (c2 - 1) * CCH + col));
            const float4 wb = __ldg(reinterpret_cast<const float4*>(W + c2 * CCH + col));
            ulonglong2* dst = reinterpret_cast<ulonglong2*>(Wx + pr * TT + col);
            dst[0] = make_ulonglong2(pack2(wa.x, wb.x), pack2(wa.y, wb.y));
            dst[1] = make_ulonglong2(pack2(wa.z, wb.z), pack2(wa.w, wb.w));
        }
        // tri slab: Wd[r*16 + i] = dup(W[r][i]), r = 0..14
        for (int k = tid; k < 240; k += BLOCK) {
            const float v = __ldg(&W[(k >> 4) * CCH + (k & 15)]);
            Wd[k] = pack2(v, v);
        }
    }
    __syncthreads();

    // ---- prefetch tile 1 into registers ----
    float4 wa[3], wb[3];
    float  tv[2];
    {
        const int cb = TT, ce = 2 * TT, tasks = (88 - 8) * 4;
        #pragma unroll
        for (int k2 = 0; k2 < 3; k2++) {
            const int task = tid + k2 * BLOCK;
            if (task < tasks) {
                const int pr = task >> 2, q = task & 3, c2 = ce + 2 * pr;
                wa[k2] = __ldg(reinterpret_cast<const float4*>(W + (c2 - 1) * CCH + cb + 4 * q));
                wb[k2] = __ldg(reinterpret_cast<const float4*>(W + c2 * CCH + cb + 4 * q));
            }
        }
        #pragma unroll
        for (int k2 = 0; k2 < 2; k2++) {
            const int idx = tid + k2 * BLOCK;
            if (idx < 240)
                tv[k2] = __ldg(&W[(cb + (idx >> 4)) * CCH + cb + (idx & 15)]);
        }
    }

    for (int t = 0; t < NTIL; t++) {
        const int cbase = t * TT;
        const int cend  = cbase + TT;
        const int pairs = 88 - 8 * t;                 // even; 0 at t=11

        // ---- x/mix for the adjacent pixel pair (LDG.64)
        float2 xv[TT], mv[TT];
        #pragma unroll
        for (int i = 0; i < TT; i++) {
            const int gi = base + ((cbase + i) << 12);
            xv[i] = __ldg(reinterpret_cast<const float2*>(x + gi));
            mv[i] = __ldg(reinterpret_cast<const float2*>(mix + gi));
        }

        // ---- sequential in-tile recurrence (scalar; builds y-dup pairs)
        float part0[TT], part1[TT];
        #pragma unroll
        for (int i = 0; i < TT; i++) { part0[i] = 0.f; part1[i] = 0.f; }

        u64 yd0[TT], yd1[TT];
        float4 a4;
        #pragma unroll
        for (int i = 0; i < TT; i++) {
            const int c = cbase + i;
            if ((i & 1) == 0) a4 = accp4[c >> 1];     // LDS.128, 2 ch x 2 px
            float m0, m1;
            if (i == 0 && t == 0) {                    // channel 0: no conv/bias
                m0 = mv[0].x;
                m1 = mv[0].y;
            } else {
                const float a0 = (i & 1) ? a4.y : a4.x;
                const float a1 = (i & 1) ? a4.w : a4.z;
                const float bb = bs[c - 1];
                m0 = a0 + bb + mv[i].x + part0[i];
                m1 = a1 + bb + mv[i].y + part1[i];
            }
            const float y0 = rintf(xv[i].x - m0) + m0; // half-to-even = jnp.round
            const float y1 = rintf(xv[i].y - m1) + m1;
            yd0[i] = pack2(y0, y0);
            yd1[i] = pack2(y1, y1);
            const int gi = base + (c << 12);
            *reinterpret_cast<float2*>(ybar_out + gi) = make_float2(y0, y1);
            *reinterpret_cast<float2*>(mix_out  + gi) = make_float2(m0, m1);
            #pragma unroll
            for (int i2 = i + 1; i2 < TT; i2++) {
                const float w = reinterpret_cast<const float*>(Wd)[2 * ((i2 - 1) * TT + i)];
                part0[i2] = fmaf(w, y0, part0[i2]);
                part1[i2] = fmaf(w, y1, part1[i2]);
            }
        }

        // ---- cross-tile rank-16 update, FFMA2 with channel-pair interleaved W
        const int kb = cend >> 1;
        for (int pr = 0; pr < pairs; pr += 2) {
            const ulonglong2* wpA = reinterpret_cast<const ulonglong2*>(Wx + (pr << 4));
            const ulonglong2* wpB = reinterpret_cast<const ulonglong2*>(Wx + ((pr + 1) << 4));
            u64 sA0 = 0, sA1 = 0, sB0 = 0, sB1 = 0;
            #pragma unroll
            for (int h = 0; h < 8; h++) {
                const ulonglong2 wA = wpA[h];
                sA0 = fma2(wA.x, yd0[2 * h], sA0); sA0 = fma2(wA.y, yd0[2 * h + 1], sA0);
                sA1 = fma2(wA.x, yd1[2 * h], sA1); sA1 = fma2(wA.y, yd1[2 * h + 1], sA1);
                const ulonglong2 wB = wpB[h];
                sB0 = fma2(wB.x, yd0[2 * h], sB0); sB0 = fma2(wB.y, yd0[2 * h + 1], sB0);
                sB1 = fma2(wB.x, yd1[2 * h], sB1); sB1 = fma2(wB.y, yd1[2 * h + 1], sB1);
            }
            float4 aA = accp4[kb + pr];
            float4 aB = accp4[kb + pr + 1];
            u64* auA = reinterpret_cast<u64*>(&aA);
            u64* auB = reinterpret_cast<u64*>(&aB);
            auA[0] = add2(auA[0], sA0); auA[1] = add2(auA[1], sA1);
            auB[0] = add2(auB[0], sB0); auB[1] = add2(auB[1], sB1);
            accp4[kb + pr]     = aA;
            accp4[kb + pr + 1] = aB;
        }

        // ---- stage slabs for t+1 from regs, prefetch t+2
        if (t + 1 < NTIL) {
            __syncthreads();
            const int pairs1 = 88 - 8 * (t + 1);
            const int tasks1 = pairs1 * 4;
            #pragma unroll
            for (int k2 = 0; k2 < 3; k2++) {
                const int task = tid + k2 * BLOCK;
                if (task < tasks1) {
                    const int pr = task >> 2, q = task & 3;
                    ulonglong2* dst = reinterpret_cast<ulonglong2*>(Wx + pr * TT + 4 * q);
                    dst[0] = make_ulonglong2(pack2(wa[k2].x, wb[k2].x), pack2(wa[k2].y, wb[k2].y));
                    dst[1] = make_ulonglong2(pack2(wa[k2].z, wb[k2].z), pack2(wa[k2].w, wb[k2].w));
                }
            }
            #pragma unroll
            for (int k2 = 0; k2 < 2; k2++) {
                const int idx = tid + k2 * BLOCK;
                if (idx < 240) Wd[idx] = pack2(tv[k2], tv[k2]);
            }
            __syncthreads();

            if (t + 2 < NTIL) {
                const int cb2 = (t + 2) * TT, ce2 = cb2 + TT;
                const int tasks2 = (88 - 8 * (t + 2)) * 4;
                #pragma unroll
                for (int k2 = 0; k2 < 3; k2++) {
                    const int task = tid + k2 * BLOCK;
                    if (task < tasks2) {
                        const int pr = task >> 2, q = task & 3, c2 = ce2 + 2 * pr;
                        wa[k2] = __ldg(reinterpret_cast<const float4*>(W + (c2 - 1) * CCH + cb2 + 4 * q));
                        wb[k2] = __ldg(reinterpret_cast<const float4*>(W + c2 * CCH + cb2 + 4 * q));
                    }
                }
                #pragma unroll
                for (int k2 = 0; k2 < 2; k2++) {
                    const int idx = tid + k2 * BLOCK;
                    if (idx < 240)
                        tv[k2] = __ldg(&W[(cb2 + (idx >> 4)) * CCH + cb2 + (idx & 15)]);
                }
            }
        }
    }
}

extern "C" void kernel_launch(void* const* d_in, const int* in_sizes, int n_in,
                              void* d_out, int out_size)
{
    const float* x   = (const float*)d_in[0];
    const float* mix = (const float*)d_in[1];
    const float* W   = (const float*)d_in[2];
    const float* b   = (const float*)d_in[3];

    float* ybar_out = (float*)d_out;
    float* mix_out  = (float*)d_out + NCHW;

    const size_t smem_bytes = (size_t)(4 * BLOCK * ACC_F4_STRIDE) * sizeof(float)
                            + (88 * TT + 240) * sizeof(u64)
                            + 191 * sizeof(float);
    cudaFuncSetAttribute(chan_deps_kernel,
                         cudaFuncAttributeMaxDynamicSharedMemorySize,
                         (int)smem_bytes);

    const int grid = NPIX / PIX_PER_BLOCK;       // 128, single balanced wave
    chan_deps_kernel<<<grid, BLOCK, smem_bytes>>>(x, mix, W, b, ybar_out, mix_out);
}